// round 2
// baseline (speedup 1.0000x reference)
#include <cuda_runtime.h>

#define NA   20000
#define NP   320000
#define FDIM 128

// ---- scratch (static device globals; no allocation) ----
__device__ int    g_cnt[NA];
__device__ int    g_cursor[NA];
__device__ int    g_off[NA + 1];
__device__ int    g_sj[NP];       // neighbor j, CSR-ordered by atom i
__device__ float4 g_su[NP];       // (ux, uy, uz, f_cutoff), CSR-ordered

// ---- K0: zero counters (must run every launch: graph replays reuse globals) ----
__global__ void k_zero() {
    int i = blockIdx.x * blockDim.x + threadIdx.x;
    if (i < NA) { g_cnt[i] = 0; g_cursor[i] = 0; }
}

// ---- K1: histogram of idx_i ----
__global__ void k_count(const int* __restrict__ idx_i) {
    int p = blockIdx.x * blockDim.x + threadIdx.x;
    if (p < NP) atomicAdd(&g_cnt[idx_i[p]], 1);
}

// ---- K2: exclusive scan of counts -> offsets (single block) ----
__global__ void k_scan() {
    __shared__ int sh[256];
    int t = threadIdx.x;
    const int CH = (NA + 255) / 256;   // 79
    int lo = t * CH;
    int hi = min(lo + CH, NA);
    int s = 0;
    for (int i = lo; i < hi; i++) s += g_cnt[i];
    sh[t] = s;
    __syncthreads();
    // Hillis-Steele inclusive scan over 256 partials
    for (int d = 1; d < 256; d <<= 1) {
        int v = (t >= d) ? sh[t - d] : 0;
        __syncthreads();
        sh[t] += v;
        __syncthreads();
    }
    int run = sh[t] - s;               // exclusive base for this chunk
    for (int i = lo; i < hi; i++) { g_off[i] = run; run += g_cnt[i]; }
    if (t == 0) g_off[NA] = sh[255];
}

// ---- K3: fill CSR-ordered pair data (j, unit vector, cutoff) ----
__global__ void k_fill(const int* __restrict__ idx_i, const int* __restrict__ idx_j,
                       const float* __restrict__ fcut, const float* __restrict__ rij) {
    int p = blockIdx.x * blockDim.x + threadIdx.x;
    if (p >= NP) return;
    int i = idx_i[p];
    int pos = atomicAdd(&g_cursor[i], 1);
    int dst = g_off[i] + pos;
    float rx = rij[3 * p + 0];
    float ry = rij[3 * p + 1];
    float rz = rij[3 * p + 2];
    float inv = rsqrtf(rx * rx + ry * ry + rz * rz);
    g_sj[dst] = idx_j[p];
    g_su[dst] = make_float4(rx * inv, ry * inv, rz * inv, fcut[p]);
}

// ---- K4: fused per-atom accumulate + matvec + norm + writeout ----
// One block per atom, 128 threads. Phase 1: thread == feature f, accumulate
// radial and V_c in registers. Phase 2: thread == output g, matvec with W
// read via __ldg (W is 64KB -> L1-resident; A is 10MB -> L2-resident).
__global__ void __launch_bounds__(128) k_main(const float* __restrict__ A,
                                              const float* __restrict__ W,
                                              const float* __restrict__ bias,
                                              float* __restrict__ out) {
    __shared__ __align__(16) float Vsh[3 * FDIM];
    __shared__ int    sj[128];
    __shared__ float4 su[128];

    int atom = blockIdx.x;
    int tid  = threadIdx.x;
    int start = g_off[atom];
    int cnt   = g_off[atom + 1] - start;

    float rad = 0.f, v0 = 0.f, v1 = 0.f, v2 = 0.f;

    for (int base = 0; base < cnt; base += 128) {
        int nc = min(128, cnt - base);
        if (tid < nc) {
            int q = start + base + tid;
            sj[tid] = g_sj[q];
            su[tid] = g_su[q];
        }
        __syncthreads();
        #pragma unroll 4
        for (int k = 0; k < nc; k++) {
            float4 uf = su[k];
            float  w  = uf.w * __ldg(&A[(long)sj[k] * FDIM + tid]);
            rad += w;
            v0  += uf.x * w;
            v1  += uf.y * w;
            v2  += uf.z * w;
        }
        __syncthreads();
    }

    Vsh[tid]            = v0;
    Vsh[FDIM + tid]     = v1;
    Vsh[2 * FDIM + tid] = v2;
    __syncthreads();

    float m0 = 0.f, m1 = 0.f, m2 = 0.f;
    const float4* Wg = reinterpret_cast<const float4*>(W + (long)tid * FDIM);
    const float4* V0 = reinterpret_cast<const float4*>(Vsh);
    const float4* V1 = reinterpret_cast<const float4*>(Vsh + FDIM);
    const float4* V2 = reinterpret_cast<const float4*>(Vsh + 2 * FDIM);
    #pragma unroll
    for (int f = 0; f < FDIM / 4; f++) {
        float4 wv = __ldg(&Wg[f]);
        float4 a = V0[f], b4 = V1[f], c = V2[f];
        m0 += wv.x * a.x  + wv.y * a.y  + wv.z * a.z  + wv.w * a.w;
        m1 += wv.x * b4.x + wv.y * b4.y + wv.z * b4.z + wv.w * b4.w;
        m2 += wv.x * c.x  + wv.y * c.y  + wv.z * c.z  + wv.w * c.w;
    }

    float bb = __ldg(&bias[tid]);
    m0 += cnt * bb; m1 += cnt * bb; m2 += cnt * bb;

    out[(long)atom * (2 * FDIM) + tid]        = sqrtf(m0 * m0 + m1 * m1 + m2 * m2 + 1e-12f);
    out[(long)atom * (2 * FDIM) + FDIM + tid] = rad;
}

extern "C" void kernel_launch(void* const* d_in, const int* in_sizes, int n_in,
                              void* d_out, int out_size) {
    const float* A    = (const float*)d_in[0];   // [NA, F]
    const int*   pl   = (const int*)  d_in[1];   // [2, NP]
    const float* fcut = (const float*)d_in[2];   // [NP, 1]
    const float* rij  = (const float*)d_in[3];   // [NP, 3]
    const float* W    = (const float*)d_in[4];   // [F, F]
    const float* bias = (const float*)d_in[5];   // [F]
    float* out = (float*)d_out;                  // [NA, 2F]

    const int* idx_i = pl;
    const int* idx_j = pl + NP;

    k_zero <<<(NA + 255) / 256, 256>>>();
    k_count<<<(NP + 255) / 256, 256>>>(idx_i);
    k_scan <<<1, 256>>>();
    k_fill <<<(NP + 255) / 256, 256>>>(idx_i, idx_j, fcut, rij);
    k_main <<<NA, 128>>>(A, W, bias, out);
}

// round 6
// speedup vs baseline: 1.6578x; 1.6578x over previous
#include <cuda_runtime.h>

#define NA   20000
#define NP   320000
#define FDIM 128

// ---- scratch (static device globals; no allocation) ----
__device__ int    g_cnt[NA];
__device__ int    g_cursor[NA];
__device__ int    g_off[NA + 1];
__device__ int    g_sj[NP];                 // neighbor j, CSR-ordered by atom i
__device__ float4 g_su[NP];                 // (ux, uy, uz, f_cutoff), CSR-ordered
__device__ __align__(16) float g_Wp[FDIM * FDIM];  // interleaved transposed W

// packed f32x2 fused multiply-add: acc = a*b + acc (elementwise on 2 floats)
#define FFMA2(acc, a, b) \
    asm("fma.rn.f32x2 %0, %1, %2, %0;" : "+l"(acc) : "l"(a), "l"(b))

// ---- K0: zero counters (graph replays reuse globals -> must zero every call) ----
__global__ void k_zero() {
    int i = blockIdx.x * blockDim.x + threadIdx.x;
    if (i < NA) { g_cnt[i] = 0; g_cursor[i] = 0; }
}

// ---- K_prep: Wp[(f>>1)*256 + 2g + (f&1)] = W[g*128 + f] ----
// A 64-bit read at Wp + (f>>1)*256 + 2g yields (W[g][2p], W[g][2p+1]),
// thread-contiguous across g -> fully coalesced.
__global__ void k_prep(const float* __restrict__ W) {
    int i = blockIdx.x * blockDim.x + threadIdx.x;   // 0..16383
    int g = i >> 7;
    int f = i & 127;
    g_Wp[(f >> 1) * 256 + 2 * g + (f & 1)] = W[g * FDIM + f];
}

// ---- K1: histogram of idx_i ----
__global__ void k_count(const int* __restrict__ idx_i) {
    int p = blockIdx.x * blockDim.x + threadIdx.x;
    if (p < NP) atomicAdd(&g_cnt[idx_i[p]], 1);
}

// ---- K2: exclusive scan of counts -> offsets (single block) ----
__global__ void k_scan() {
    __shared__ int sh[256];
    int t = threadIdx.x;
    const int CH = (NA + 255) / 256;
    int lo = t * CH;
    int hi = min(lo + CH, NA);
    int s = 0;
    for (int i = lo; i < hi; i++) s += g_cnt[i];
    sh[t] = s;
    __syncthreads();
    for (int d = 1; d < 256; d <<= 1) {
        int v = (t >= d) ? sh[t - d] : 0;
        __syncthreads();
        sh[t] += v;
        __syncthreads();
    }
    int run = sh[t] - s;
    for (int i = lo; i < hi; i++) { g_off[i] = run; run += g_cnt[i]; }
    if (t == 0) g_off[NA] = sh[255];
}

// ---- K3: fill CSR-ordered pair data ----
__global__ void k_fill(const int* __restrict__ idx_i, const int* __restrict__ idx_j,
                       const float* __restrict__ fcut, const float* __restrict__ rij) {
    int p = blockIdx.x * blockDim.x + threadIdx.x;
    if (p >= NP) return;
    int i = idx_i[p];
    int pos = atomicAdd(&g_cursor[i], 1);
    int dst = g_off[i] + pos;
    float rx = rij[3 * p + 0];
    float ry = rij[3 * p + 1];
    float rz = rij[3 * p + 2];
    float inv = rsqrtf(rx * rx + ry * ry + rz * rz);
    g_sj[dst] = idx_j[p];
    g_su[dst] = make_float4(rx * inv, ry * inv, rz * inv, fcut[p]);
}

// ---- K4: fused per-atom accumulate + coalesced packed matvec + norm ----
__global__ void __launch_bounds__(128, 6) k_main(const float* __restrict__ A,
                                                 const float* __restrict__ bias,
                                                 float* __restrict__ out) {
    __shared__ __align__(16) float Vsh[3 * FDIM];
    __shared__ int    sj[128];
    __shared__ float4 su[128];

    int atom = blockIdx.x;
    int tid  = threadIdx.x;
    int start = g_off[atom];
    int cnt   = g_off[atom + 1] - start;

    // ---- phase 1: per-feature accumulation (thread == feature f = tid) ----
    float rad = 0.f, v0 = 0.f, v1 = 0.f, v2 = 0.f;
    for (int base = 0; base < cnt; base += 128) {
        int nc = min(128, cnt - base);
        if (tid < nc) {
            int q = start + base + tid;
            sj[tid] = g_sj[q];
            su[tid] = g_su[q];
        }
        __syncthreads();
        #pragma unroll 4
        for (int k = 0; k < nc; k++) {
            float4 uf = su[k];
            float  w  = uf.w * __ldg(&A[(long)sj[k] * FDIM + tid]);
            rad += w;
            v0  += uf.x * w;
            v1  += uf.y * w;
            v2  += uf.z * w;
        }
        __syncthreads();
    }

    Vsh[tid]            = v0;
    Vsh[FDIM + tid]     = v1;
    Vsh[2 * FDIM + tid] = v2;
    __syncthreads();

    // ---- phase 2: matvec y[g] = sum_f V[f] * W[g,f] (thread == output g = tid) ----
    // Wp interleaved: one 64-bit load = (W[g,2p], W[g,2p+1]), coalesced.
    // Even-f terms accumulate in .lo, odd-f in .hi of packed f32x2 accumulators.
    const unsigned long long* Wp64 = (const unsigned long long*)g_Wp;
    const ulonglong2* V0 = (const ulonglong2*)(Vsh);
    const ulonglong2* V1 = (const ulonglong2*)(Vsh + FDIM);
    const ulonglong2* V2 = (const ulonglong2*)(Vsh + 2 * FDIM);

    unsigned long long A0 = 0ull, A1 = 0ull, A2 = 0ull;
    #pragma unroll 16
    for (int i = 0; i < FDIM / 4; i++) {
        unsigned long long w0 = __ldg(&Wp64[i * 256 + tid]);        // f-pair 2i
        unsigned long long w1 = __ldg(&Wp64[i * 256 + 128 + tid]);  // f-pair 2i+1
        ulonglong2 a = V0[i];
        ulonglong2 b = V1[i];
        ulonglong2 c = V2[i];
        FFMA2(A0, w0, a.x); FFMA2(A0, w1, a.y);
        FFMA2(A1, w0, b.x); FFMA2(A1, w1, b.y);
        FFMA2(A2, w0, c.x); FFMA2(A2, w1, c.y);
    }

    float2 p0 = *reinterpret_cast<float2*>(&A0);
    float2 p1 = *reinterpret_cast<float2*>(&A1);
    float2 p2 = *reinterpret_cast<float2*>(&A2);
    float bb = __ldg(&bias[tid]);
    float m0 = p0.x + p0.y + cnt * bb;
    float m1 = p1.x + p1.y + cnt * bb;
    float m2 = p2.x + p2.y + cnt * bb;

    out[(long)atom * (2 * FDIM) + tid]        = sqrtf(m0 * m0 + m1 * m1 + m2 * m2 + 1e-12f);
    out[(long)atom * (2 * FDIM) + FDIM + tid] = rad;
}

extern "C" void kernel_launch(void* const* d_in, const int* in_sizes, int n_in,
                              void* d_out, int out_size) {
    const float* A    = (const float*)d_in[0];   // [NA, F]
    const int*   pl   = (const int*)  d_in[1];   // [2, NP]
    const float* fcut = (const float*)d_in[2];   // [NP, 1]
    const float* rij  = (const float*)d_in[3];   // [NP, 3]
    const float* W    = (const float*)d_in[4];   // [F, F]
    const float* bias = (const float*)d_in[5];   // [F]
    float* out = (float*)d_out;                  // [NA, 2F]

    const int* idx_i = pl;
    const int* idx_j = pl + NP;

    k_zero <<<(NA + 255) / 256, 256>>>();
    k_prep <<<(FDIM * FDIM + 255) / 256, 256>>>(W);
    k_count<<<(NP + 255) / 256, 256>>>(idx_i);
    k_scan <<<1, 256>>>();
    k_fill <<<(NP + 255) / 256, 256>>>(idx_i, idx_j, fcut, rij);
    k_main <<<NA, 128>>>(A, bias, out);
}